// round 1
// baseline (speedup 1.0000x reference)
#include <cuda_runtime.h>

#define B_N 128
#define S_N 1024
#define T_N 128
#define NTH 256
#define SOS_T 0
#define EOS_T 1

__device__ float g_res[B_N];

typedef unsigned long long u64;

static __device__ __forceinline__ u64 pk2(float x, float y) {
    u64 r; asm("mov.b64 %0, {%1,%2};" : "=l"(r) : "f"(x), "f"(y)); return r;
}
static __device__ __forceinline__ void upk2(u64 v, float &x, float &y) {
    asm("mov.b64 {%0,%1}, %2;" : "=f"(x), "=f"(y) : "l"(v));
}
static __device__ __forceinline__ u64 fma2(u64 a, u64 b, u64 c) {
    u64 d; asm("fma.rn.f32x2 %0, %1, %2, %3;" : "=l"(d) : "l"(a), "l"(b), "l"(c)); return d;
}
static __device__ __forceinline__ u64 add2(u64 a, u64 b) {
    u64 d; asm("add.rn.f32x2 %0, %1, %2;" : "=l"(d) : "l"(a), "l"(b)); return d;
}
static __device__ __forceinline__ float ex2a(float x) {
    float r; asm("ex2.approx.f32 %0, %1;" : "=f"(r) : "f"(x)); return r;
}
static __device__ __forceinline__ float lg2a(float x) {
    float r; asm("lg2.approx.f32 %0, %1;" : "=f"(r) : "f"(x)); return r;
}

// One CTA per batch. 256 threads: thread tid handles column j = tid>>1 with
// i-half selected by tid&1. exp(T) tile (64 values) lives in registers.
// Recurrence in linear space with stale-by-two max normalization:
//   alpha'_j = m_used + ln( sum_i exp(alpha_i - m_used) * expT[i][j] ) + e_j
__global__ void __launch_bounds__(NTH, 1) crf_fwd(
    const float* __restrict__ em, const float* __restrict__ tr,
    const float* __restrict__ mk, const int* __restrict__ tg)
{
    const int b   = blockIdx.x;
    const int tid = threadIdx.x;
    const int j   = tid >> 1;
    const int odd = tid & 1;
    const int ihalf = odd << 6;   // 0 or 64

    __shared__ __align__(16) float s_v[2][T_N];      // exp(alpha - m), double buffered
    __shared__ __align__(16) float s_alpha[2][T_N];  // alpha, double buffered
    __shared__ __align__(16) float s_m8[2][8];       // per-warp maxes, double buffered
    __shared__ float s_red[NTH];
    __shared__ int   s_cnt[NTH];
    __shared__ float s_score;

    const float* emb = em + (size_t)b * S_N * T_N;
    const float* mkb = mk + (size_t)b * S_N;
    const int*   tgb = tg + (size_t)b * S_N;

    const float L2E = 1.4426950408889634f;
    const float LN2 = 0.6931471805599453f;

    // ---------------- gold path score ----------------
    {
        float sp = 0.f; int cnt = 0;
        for (int s = tid; s < S_N; s += NTH) {
            float mv = mkb[s];
            cnt += (int)mv;
            if (s >= 1) {
                int t1  = tgb[s];
                int t0p = tgb[s - 1];
                sp += (emb[(size_t)s * T_N + t1] + tr[t0p * T_N + t1]) * mv;
            }
        }
        s_red[tid] = sp; s_cnt[tid] = cnt;
        __syncthreads();
        for (int st = NTH >> 1; st > 0; st >>= 1) {
            if (tid < st) { s_red[tid] += s_red[tid + st]; s_cnt[tid] += s_cnt[tid + st]; }
            __syncthreads();
        }
        if (tid == 0) {
            int last = s_cnt[0] - 1;
            int t0   = tgb[0];
            int lt   = tgb[last];
            s_score = s_red[0] + tr[SOS_T * T_N + t0] + emb[t0] + tr[lt * T_N + EOS_T];
        }
    }

    // ---------------- transition tile in registers (exp domain) ----------------
    // E[p] packs expT[i][j], expT[i+1][j] for i = ihalf + 2p.
    u64 E[32];
    #pragma unroll
    for (int p = 0; p < 32; p++) {
        int i = ihalf + 2 * p;
        float a = exp2f(tr[i * T_N + j] * L2E);
        float c = exp2f(tr[(i + 1) * T_N + j] * L2E);
        E[p] = pk2(a, c);
    }

    // ---------------- alpha0, m0, v0 ----------------
    float alpha = tr[SOS_T * T_N + j] + emb[j];
    if (!odd) s_alpha[0][j] = alpha;
    __syncthreads();
    if (tid < 32) {
        float4 z = *(const float4*)&s_alpha[0][tid * 4];
        float mx = fmaxf(fmaxf(z.x, z.y), fmaxf(z.z, z.w));
        #pragma unroll
        for (int msk = 16; msk >= 1; msk >>= 1)
            mx = fmaxf(mx, __shfl_xor_sync(0xffffffffu, mx, msk));
        if (tid == 0) {
            #pragma unroll
            for (int k = 0; k < 8; k++) { s_m8[0][k] = mx; s_m8[1][k] = mx; }
        }
    }
    __syncthreads();
    float m_used = s_m8[0][0];
    if (!odd) s_v[1][j] = ex2a((alpha - m_used) * L2E);  // step 1 reads buffer s&1 = 1

    // register prefetch pipeline (distance 2) for emissions + mask
    float eA = 0.f, eB = 0.f, mA = 1.f, mB = 1.f;
    if (!odd) {
        eA = emb[(size_t)1 * T_N + j];  mA = mkb[1];
        eB = emb[(size_t)2 * T_N + j];  mB = mkb[2];
    }
    __syncthreads();

    // ---------------- recurrence: 1023 sequential steps ----------------
    for (int s = 1; s < S_N; s++) {
        float eN = 0.f, mN = 1.f, mglob = 0.f;
        if (!odd) {
            int sp2 = (s + 2 < S_N) ? (s + 2) : (S_N - 1);
            eN = emb[(size_t)sp2 * T_N + j];
            mN = mkb[sp2];
            // stale-by-two max (written 1 step ago, barrier in between)
            const float* mmp = s_m8[(s + 1) & 1];
            float4 a = *(const float4*)mmp;
            float4 c = *(const float4*)(mmp + 4);
            mglob = fmaxf(fmaxf(fmaxf(a.x, a.y), fmaxf(a.z, a.w)),
                          fmaxf(fmaxf(c.x, c.y), fmaxf(c.z, c.w)));
        } else {
            // odd lanes: compute warp-max of alpha_{s-1} (overlapped with matvec)
            float ap = s_alpha[(s + 1) & 1][j];
            #pragma unroll
            for (int msk = 2; msk <= 16; msk <<= 1)
                ap = fmaxf(ap, __shfl_xor_sync(0xAAAAAAAAu, ap, msk));
            if ((tid & 31) == 1) s_m8[s & 1][tid >> 5] = ap;
        }

        // matvec half-column: w_part = sum_{i in half} v[i] * expT[i][j]
        const float* vcur = s_v[s & 1];
        u64 acc[8];
        #pragma unroll
        for (int q = 0; q < 8; q++) acc[q] = 0ull;
        #pragma unroll
        for (int k = 0; k < 8; k++) {
            float4 va = *(const float4*)&vcur[ihalf + k * 8];
            float4 vb = *(const float4*)&vcur[ihalf + k * 8 + 4];
            int qb = (k & 1) << 2;
            acc[qb + 0] = fma2(E[k * 4 + 0], pk2(va.x, va.y), acc[qb + 0]);
            acc[qb + 1] = fma2(E[k * 4 + 1], pk2(va.z, va.w), acc[qb + 1]);
            acc[qb + 2] = fma2(E[k * 4 + 2], pk2(vb.x, vb.y), acc[qb + 2]);
            acc[qb + 3] = fma2(E[k * 4 + 3], pk2(vb.z, vb.w), acc[qb + 3]);
        }
        u64 t0 = add2(add2(acc[0], acc[1]), add2(acc[2], acc[3]));
        u64 t1 = add2(add2(acc[4], acc[5]), add2(acc[6], acc[7]));
        u64 tt = add2(t0, t1);
        float tx, ty; upk2(tt, tx, ty);
        float wp = tx + ty;
        wp += __shfl_xor_sync(0xffffffffu, wp, 1);   // combine the two i-halves

        if (!odd) {
            wp = fmaxf(wp, 1e-33f);  // keep -10000-ish states finite (contributions ~e^-69, negligible)
            float anew = m_used + lg2a(wp) * LN2 + eA;
            alpha = mA * anew + (1.f - mA) * alpha;  // mask blend
            s_alpha[s & 1][j] = alpha;
            s_v[(s + 1) & 1][j] = ex2a((alpha - mglob) * L2E);
            m_used = mglob;
            eA = eB; eB = eN; mA = mB; mB = mN;
        }
        __syncthreads();
    }

    // ---------------- partition + per-batch result ----------------
    if (tid < 32) {
        const float* af = s_alpha[(S_N - 1) & 1];
        float z0 = af[tid * 4 + 0] + tr[(tid * 4 + 0) * T_N + EOS_T];
        float z1 = af[tid * 4 + 1] + tr[(tid * 4 + 1) * T_N + EOS_T];
        float z2 = af[tid * 4 + 2] + tr[(tid * 4 + 2) * T_N + EOS_T];
        float z3 = af[tid * 4 + 3] + tr[(tid * 4 + 3) * T_N + EOS_T];
        float mx = fmaxf(fmaxf(z0, z1), fmaxf(z2, z3));
        #pragma unroll
        for (int msk = 16; msk >= 1; msk >>= 1)
            mx = fmaxf(mx, __shfl_xor_sync(0xffffffffu, mx, msk));
        float sm = ex2a((z0 - mx) * L2E) + ex2a((z1 - mx) * L2E)
                 + ex2a((z2 - mx) * L2E) + ex2a((z3 - mx) * L2E);
        #pragma unroll
        for (int msk = 16; msk >= 1; msk >>= 1)
            sm += __shfl_xor_sync(0xffffffffu, sm, msk);
        if (tid == 0) {
            float partition = mx + lg2a(sm) * LN2;
            g_res[b] = s_score - partition;
        }
    }
}

__global__ void crf_reduce(float* out) {
    int tid = threadIdx.x;  // 128 threads
    __shared__ float sh[4];
    float v = g_res[tid];
    #pragma unroll
    for (int msk = 16; msk >= 1; msk >>= 1)
        v += __shfl_xor_sync(0xffffffffu, v, msk);
    if ((tid & 31) == 0) sh[tid >> 5] = v;
    __syncthreads();
    if (tid == 0) out[0] = -(sh[0] + sh[1] + sh[2] + sh[3]);
}

extern "C" void kernel_launch(void* const* d_in, const int* in_sizes, int n_in,
                              void* d_out, int out_size) {
    (void)in_sizes; (void)n_in; (void)out_size;
    const float* em = (const float*)d_in[0];   // emissions [128,1024,128] f32
    const float* tr = (const float*)d_in[1];   // transition [128,128] f32
    const float* mk = (const float*)d_in[2];   // mask [128,1024] f32
    const int*   tg = (const int*)d_in[3];     // tags [128,1024] i32
    crf_fwd<<<B_N, NTH>>>(em, tr, mk, tg);
    crf_reduce<<<1, B_N>>>((float*)d_out);
}

// round 2
// speedup vs baseline: 2.2721x; 2.2721x over previous
#include <cuda_runtime.h>

#define B_N 128
#define S_N 1024
#define T_N 128
#define NTH 128
#define SOS_T 0
#define EOS_T 1

__device__ float g_res[B_N];

typedef unsigned long long u64;

static __device__ __forceinline__ u64 pk2(float x, float y) {
    u64 r; asm("mov.b64 %0, {%1,%2};" : "=l"(r) : "f"(x), "f"(y)); return r;
}
static __device__ __forceinline__ void upk2(u64 v, float &x, float &y) {
    asm("mov.b64 {%0,%1}, %2;" : "=f"(x), "=f"(y) : "l"(v));
}
static __device__ __forceinline__ u64 fma2(u64 a, u64 b, u64 c) {
    u64 d; asm("fma.rn.f32x2 %0, %1, %2, %3;" : "=l"(d) : "l"(a), "l"(b), "l"(c)); return d;
}
static __device__ __forceinline__ u64 add2(u64 a, u64 b) {
    u64 d; asm("add.rn.f32x2 %0, %1, %2;" : "=l"(d) : "l"(a), "l"(b)); return d;
}
static __device__ __forceinline__ float ex2a(float x) {
    float r; asm("ex2.approx.f32 %0, %1;" : "=f"(r) : "f"(x)); return r;
}
static __device__ __forceinline__ float lg2a(float x) {
    float r; asm("lg2.approx.f32 %0, %1;" : "=f"(r) : "f"(x)); return r;
}

// One CTA per batch, 128 threads, thread j owns column j of alpha.
// Linear-space recurrence with a scalar normalizer (alpha[2], stale by 2 steps):
//   alpha'_j = m + ln( sum_i exp(alpha_i - m) * expT[i][j] ) + e_j
// exp(T) column lives in registers (64 packed f32x2 = 128 regs).
__global__ void __launch_bounds__(NTH, 1) crf_fwd(
    const float* __restrict__ em, const float* __restrict__ tr,
    const float* __restrict__ mk, const int* __restrict__ tg)
{
    const int b = blockIdx.x;
    const int j = threadIdx.x;

    __shared__ __align__(16) float s_v[2][T_N];   // exp(alpha - m), double buffered
    __shared__ float s_norm[2];                   // scalar normalizer, double buffered
    __shared__ __align__(16) float s_red[NTH];
    __shared__ int   s_cnt[NTH];
    __shared__ float s_score;

    const float* emb = em + (size_t)b * S_N * T_N;
    const float* mkb = mk + (size_t)b * S_N;
    const int*   tgb = tg + (size_t)b * S_N;

    const float L2E = 1.4426950408889634f;
    const float LN2 = 0.6931471805599453f;

    // ---------------- gold path score ----------------
    {
        float sp = 0.f; int cnt = 0;
        for (int s = j; s < S_N; s += NTH) {
            float mv = mkb[s];
            cnt += (int)mv;
            if (s >= 1) {
                int t1  = tgb[s];
                int t0p = tgb[s - 1];
                sp += (emb[(size_t)s * T_N + t1] + tr[t0p * T_N + t1]) * mv;
            }
        }
        s_red[j] = sp; s_cnt[j] = cnt;
        __syncthreads();
        for (int st = NTH >> 1; st > 0; st >>= 1) {
            if (j < st) { s_red[j] += s_red[j + st]; s_cnt[j] += s_cnt[j + st]; }
            __syncthreads();
        }
        if (j == 0) {
            int last = s_cnt[0] - 1;
            int t0   = tgb[0];
            int lt   = tgb[last];
            s_score = s_red[0] + tr[SOS_T * T_N + t0] + emb[t0] + tr[lt * T_N + EOS_T];
        }
        __syncthreads();
    }

    // ---------------- transition column in registers (exp domain) ----------------
    // E[p] packs expT[2p][j], expT[2p+1][j].
    u64 E[64];
    #pragma unroll
    for (int p = 0; p < 64; p++) {
        float a = ex2a(tr[(2 * p)     * T_N + j] * L2E);
        float c = ex2a(tr[(2 * p + 1) * T_N + j] * L2E);
        E[p] = pk2(a, c);
    }

    // ---------------- alpha0, m0, v0 ----------------
    float alpha = tr[SOS_T * T_N + j] + emb[j];
    s_red[j] = alpha;
    __syncthreads();
    if (j < 32) {
        float mx = fmaxf(fmaxf(s_red[j], s_red[j + 32]),
                         fmaxf(s_red[j + 64], s_red[j + 96]));
        #pragma unroll
        for (int msk = 16; msk >= 1; msk >>= 1)
            mx = fmaxf(mx, __shfl_xor_sync(0xffffffffu, mx, msk));
        if (j == 0) s_norm[0] = mx;
    }
    __syncthreads();
    float m_used = s_norm[0];
    s_v[1][j] = ex2a((alpha - m_used) * L2E);   // step 1 reads buffer s&1 = 1

    // emission/mask register prefetch, distance 2
    float eA = emb[(size_t)1 * T_N + j];
    float mA = mkb[1];
    float eB = emb[(size_t)2 * T_N + j];
    float mB = mkb[2];
    __syncthreads();

    // ---------------- recurrence: 1023 sequential steps ----------------
    for (int s = 1; s < S_N; s++) {
        int sp2 = (s + 2 < S_N) ? (s + 2) : (S_N - 1);
        float eN = emb[(size_t)sp2 * T_N + j];
        float mN = mkb[sp2];
        float m_next = s_norm[(s - 1) & 1];   // alpha_{s-2}[2] (or m0), race-free

        const float* vcur = s_v[s & 1];
        u64 acc[8];
        #pragma unroll
        for (int q = 0; q < 8; q++) acc[q] = 0ull;
        #pragma unroll
        for (int k = 0; k < 16; k++) {
            float4 va = *(const float4*)&vcur[k * 8];
            float4 vb = *(const float4*)&vcur[k * 8 + 4];
            int qb = (k & 1) << 2;
            acc[qb + 0] = fma2(E[k * 4 + 0], pk2(va.x, va.y), acc[qb + 0]);
            acc[qb + 1] = fma2(E[k * 4 + 1], pk2(va.z, va.w), acc[qb + 1]);
            acc[qb + 2] = fma2(E[k * 4 + 2], pk2(vb.x, vb.y), acc[qb + 2]);
            acc[qb + 3] = fma2(E[k * 4 + 3], pk2(vb.z, vb.w), acc[qb + 3]);
        }
        u64 t0 = add2(add2(acc[0], acc[1]), add2(acc[2], acc[3]));
        u64 t1 = add2(add2(acc[4], acc[5]), add2(acc[6], acc[7]));
        u64 tt = add2(t0, t1);
        float tx, ty; upk2(tt, tx, ty);
        float wp = tx + ty;

        wp = fmaxf(wp, 1e-33f);                    // SOS column sums to 0; keep finite
        float anew = m_used + lg2a(wp) * LN2 + eA;
        alpha = fmaf(mA, anew - alpha, alpha);     // mask blend
        if (j == 2) s_norm[s & 1] = alpha;         // normalizer for step s+2
        s_v[(s + 1) & 1][j] = ex2a((alpha - m_next) * L2E);
        m_used = m_next;
        eA = eB; eB = eN; mA = mB; mB = mN;
        __syncthreads();
    }

    // ---------------- partition + per-batch result ----------------
    {
        float z = alpha + tr[j * T_N + EOS_T];
        s_red[j] = z;
        __syncthreads();
        if (j < 32) {
            float z0 = s_red[j], z1 = s_red[j + 32], z2 = s_red[j + 64], z3 = s_red[j + 96];
            float mx = fmaxf(fmaxf(z0, z1), fmaxf(z2, z3));
            #pragma unroll
            for (int msk = 16; msk >= 1; msk >>= 1)
                mx = fmaxf(mx, __shfl_xor_sync(0xffffffffu, mx, msk));
            float sm = ex2a((z0 - mx) * L2E) + ex2a((z1 - mx) * L2E)
                     + ex2a((z2 - mx) * L2E) + ex2a((z3 - mx) * L2E);
            #pragma unroll
            for (int msk = 16; msk >= 1; msk >>= 1)
                sm += __shfl_xor_sync(0xffffffffu, sm, msk);
            if (j == 0) {
                float partition = mx + lg2a(sm) * LN2;
                g_res[b] = s_score - partition;
            }
        }
    }
}

__global__ void crf_reduce(float* out) {
    int tid = threadIdx.x;  // 128 threads
    __shared__ float sh[4];
    float v = g_res[tid];
    #pragma unroll
    for (int msk = 16; msk >= 1; msk >>= 1)
        v += __shfl_xor_sync(0xffffffffu, v, msk);
    if ((tid & 31) == 0) sh[tid >> 5] = v;
    __syncthreads();
    if (tid == 0) out[0] = -(sh[0] + sh[1] + sh[2] + sh[3]);
}

extern "C" void kernel_launch(void* const* d_in, const int* in_sizes, int n_in,
                              void* d_out, int out_size) {
    (void)in_sizes; (void)n_in; (void)out_size;
    const float* em = (const float*)d_in[0];   // emissions [128,1024,128] f32
    const float* tr = (const float*)d_in[1];   // transition [128,128] f32
    const float* mk = (const float*)d_in[2];   // mask [128,1024] f32
    const int*   tg = (const int*)d_in[3];     // tags [128,1024] i32
    crf_fwd<<<B_N, NTH>>>(em, tr, mk, tg);
    crf_reduce<<<1, B_N>>>((float*)d_out);
}